// round 12
// baseline (speedup 1.0000x reference)
#include <cuda_runtime.h>
#include <cuda_bf16.h>
#include <cstdint>

namespace {
constexpr int H  = 16;
constexpr int D  = 1024;
constexpr int B  = 4;
constexpr int SQ = 1024;
constexpr int SK = 1024;
constexpr float INV_SCALE = 1.0f / 32.0f;

constexpr int KC    = 64;                    // K-chunk
constexpr int KSE   = 72;                    // smem row stride (elems)
constexpr int TBA   = 128 * KSE * 2;         // 18432 B
constexpr int TBA2  = 256 * KSE * 2;         // 36864 B
constexpr int TBB64 = 64 * KSE * 2;          // 9216 B
constexpr int STAGE_P  = 2 * TBA + 2 * TBA2;    // 110592 (A128 hi/lo + B256 hi/lo)
constexpr int SMEM_P2  = 2 * STAGE_P;           // 221184 (2-stage)
constexpr int SMEM_SC1 = STAGE_P;               // scores: single stage
constexpr int STAGE_AV = 2 * TBA2 + 2 * TBB64;  // 92160  (A256 hi/lo + B64 hi/lo)
constexpr int SMEM_AV2 = 2 * STAGE_AV;          // 184320
}

// ------------------------- global scratch (bf16 hi/lo) ----------------------
__device__ __nv_bfloat16 g_xhi[3u * 4 * 1024 * 1024];
__device__ __nv_bfloat16 g_xlo[3u * 4 * 1024 * 1024];
__device__ __nv_bfloat16 g_wthi[3u * 1024 * 1024];   // [p][n=h*64+c][d]
__device__ __nv_bfloat16 g_wtlo[3u * 1024 * 1024];
__device__ __nv_bfloat16 g_qhi[64u * 1024 * 64];     // [bh][s][k]
__device__ __nv_bfloat16 g_qlo[64u * 1024 * 64];
__device__ __nv_bfloat16 g_khi[64u * 1024 * 64];
__device__ __nv_bfloat16 g_klo[64u * 1024 * 64];
__device__ __nv_bfloat16 g_vthi[64u * 64 * 1024];    // [bh][v][s]
__device__ __nv_bfloat16 g_vtlo[64u * 64 * 1024];
__device__ __nv_bfloat16 g_phi[64u * 1024 * 1024];   // [h*B+b][q][s]
__device__ __nv_bfloat16 g_plo[64u * 1024 * 1024];
__device__ __nv_bfloat16 g_ctxhi[4096u * 1024];      // [b*q][h*64+v]
__device__ __nv_bfloat16 g_ctxlo[4096u * 1024];
__device__ __nv_bfloat16 g_wphi[1024u * 1024];       // [n][k]
__device__ __nv_bfloat16 g_wplo[1024u * 1024];

// ------------------------------ helpers -------------------------------------
__device__ __forceinline__ uint32_t cvta_s(const void* p) {
  uint32_t a;
  asm("{ .reg .u64 t; cvta.to.shared.u64 t, %1; cvt.u32.u64 %0, t; }" : "=r"(a) : "l"(p));
  return a;
}
__device__ __forceinline__ void cp16(uint32_t d, const void* s) {
  asm volatile("cp.async.ca.shared.global [%0], [%1], 16;" :: "r"(d), "l"(s));
}
__device__ __forceinline__ void cp_commit() { asm volatile("cp.async.commit_group;" ::: "memory"); }
__device__ __forceinline__ void cp_wait0()  { asm volatile("cp.async.wait_group 0;" ::: "memory"); }
__device__ __forceinline__ void cp_wait1()  { asm volatile("cp.async.wait_group 1;" ::: "memory"); }

__device__ __forceinline__ void ldm4(uint32_t& r0, uint32_t& r1, uint32_t& r2, uint32_t& r3,
                                     uint32_t a) {
  asm volatile("ldmatrix.sync.aligned.m8n8.x4.shared.b16 {%0,%1,%2,%3}, [%4];"
               : "=r"(r0), "=r"(r1), "=r"(r2), "=r"(r3) : "r"(a));
}
__device__ __forceinline__ void mma_bf16(float* c, const uint32_t* a, uint32_t b0, uint32_t b1) {
  asm volatile(
      "mma.sync.aligned.m16n8k16.row.col.f32.bf16.bf16.f32 "
      "{%0,%1,%2,%3}, {%4,%5,%6,%7}, {%8,%9}, {%0,%1,%2,%3};"
      : "+f"(c[0]), "+f"(c[1]), "+f"(c[2]), "+f"(c[3])
      : "r"(a[0]), "r"(a[1]), "r"(a[2]), "r"(a[3]), "r"(b0), "r"(b1));
}

__device__ __forceinline__ void split_pack(float a, float b, uint32_t& hi, uint32_t& lo) {
  __nv_bfloat16 h0 = __float2bfloat16(a), h1 = __float2bfloat16(b);
  __nv_bfloat16 l0 = __float2bfloat16(a - __bfloat162float(h0));
  __nv_bfloat16 l1 = __float2bfloat16(b - __bfloat162float(h1));
  hi = (uint32_t)__bfloat16_as_ushort(h0) | ((uint32_t)__bfloat16_as_ushort(h1) << 16);
  lo = (uint32_t)__bfloat16_as_ushort(l0) | ((uint32_t)__bfloat16_as_ushort(l1) << 16);
}

// fill ROWS x 64-k tile via cp.async with NT threads
template <int ROWS, int NT>
__device__ __forceinline__ void fillT(uint32_t sbase, const __nv_bfloat16* g,
                                      int rstride, int t) {
  #pragma unroll
  for (int i = 0; i < ROWS * 8 / NT; ++i) {
    int f = t + i * NT;
    int r = f >> 3, ck = (f & 7) * 8;
    cp16(sbase + (uint32_t)(r * KSE + ck) * 2, g + (size_t)r * rstride + ck);
  }
}

// Wide warp tile: MI*16 rows x NI*16 cols, 3-term split MMA over one 64-k chunk.
// acc[MI][2*NI][4]. B frags loaded per-ni to bound register liveness.
template <int MI, int NI>
__device__ __forceinline__ void mma_tile_w(float (*acc)[2 * NI][4],
                                           uint32_t sAh, uint32_t sAl,
                                           uint32_t sBh, uint32_t sBl,
                                           int arow0, int brow0) {
  int lane = threadIdx.x & 31;
  int lr = lane & 15, lh = lane >> 4;
  #pragma unroll
  for (int ks = 0; ks < KC; ks += 16) {
    int ko = ks + lh * 8;
    uint32_t ah[MI][4], al[MI][4];
    #pragma unroll
    for (int mi = 0; mi < MI; ++mi) {
      uint32_t off = (uint32_t)((arow0 + mi * 16 + lr) * KSE + ko) * 2;
      ldm4(ah[mi][0], ah[mi][1], ah[mi][2], ah[mi][3], sAh + off);
      ldm4(al[mi][0], al[mi][1], al[mi][2], al[mi][3], sAl + off);
    }
    #pragma unroll
    for (int ni = 0; ni < NI; ++ni) {
      uint32_t bh[4], bl[4];
      uint32_t off = (uint32_t)((brow0 + ni * 16 + lr) * KSE + ko) * 2;
      ldm4(bh[0], bh[1], bh[2], bh[3], sBh + off);
      ldm4(bl[0], bl[1], bl[2], bl[3], sBl + off);
      #pragma unroll
      for (int mi = 0; mi < MI; ++mi) {
        mma_bf16(acc[mi][2 * ni],     ah[mi], bh[0], bh[2]);
        mma_bf16(acc[mi][2 * ni],     al[mi], bh[0], bh[2]);
        mma_bf16(acc[mi][2 * ni],     ah[mi], bl[0], bl[2]);
        mma_bf16(acc[mi][2 * ni + 1], ah[mi], bh[1], bh[3]);
        mma_bf16(acc[mi][2 * ni + 1], al[mi], bh[1], bh[3]);
        mma_bf16(acc[mi][2 * ni + 1], ah[mi], bl[1], bl[3]);
      }
    }
  }
}

// -------------------------- pre-pass conversions ----------------------------
__global__ __launch_bounds__(256) void conv_x(const float* __restrict__ query,
                                              const float* __restrict__ key,
                                              const float* __restrict__ value) {
  int p = blockIdx.y;
  const float* src = (p == 0) ? query : (p == 1) ? key : value;
  size_t i = ((size_t)blockIdx.x * 256 + threadIdx.x) * 4;
  float4 v = *reinterpret_cast<const float4*>(src + i);
  size_t o = (size_t)p * 4 * 1024 * 1024 + i;
  uint32_t h0, l0, h1, l1;
  split_pack(v.x, v.y, h0, l0);
  split_pack(v.z, v.w, h1, l1);
  *(uint32_t*)(g_xhi + o)     = h0;  *(uint32_t*)(g_xhi + o + 2) = h1;
  *(uint32_t*)(g_xlo + o)     = l0;  *(uint32_t*)(g_xlo + o + 2) = l1;
}

__global__ __launch_bounds__(256) void conv_w(const float* __restrict__ w_q,
                                              const float* __restrict__ w_k,
                                              const float* __restrict__ w_v) {
  int p = blockIdx.y, n = blockIdx.x;
  const float* W = (p == 0) ? w_q : (p == 1) ? w_k : w_v;
  int h = n >> 6, c = n & 63;
  int d0 = threadIdx.x * 4;
  float a = W[(size_t)h * 65536 + (size_t)(d0 + 0) * 64 + c];
  float b = W[(size_t)h * 65536 + (size_t)(d0 + 1) * 64 + c];
  float e = W[(size_t)h * 65536 + (size_t)(d0 + 2) * 64 + c];
  float f = W[(size_t)h * 65536 + (size_t)(d0 + 3) * 64 + c];
  size_t o = ((size_t)p * 1024 + n) * 1024 + d0;
  uint32_t h0, l0, h1, l1;
  split_pack(a, b, h0, l0);
  split_pack(e, f, h1, l1);
  *(uint32_t*)(g_wthi + o)     = h0;  *(uint32_t*)(g_wthi + o + 2) = h1;
  *(uint32_t*)(g_wtlo + o)     = l0;  *(uint32_t*)(g_wtlo + o + 2) = l1;
}

__global__ __launch_bounds__(256) void conv_wp(const float* __restrict__ w_proj) {
  int n = blockIdx.x;
  int k0 = threadIdx.x * 4;
  float4 v = *reinterpret_cast<const float4*>(w_proj + (size_t)n * 1024 + k0);
  size_t o = (size_t)n * 1024 + k0;
  uint32_t h0, l0, h1, l1;
  split_pack(v.x, v.y, h0, l0);
  split_pack(v.z, v.w, h1, l1);
  *(uint32_t*)(g_wphi + o)     = h0;  *(uint32_t*)(g_wphi + o + 2) = h1;
  *(uint32_t*)(g_wplo + o)     = l0;  *(uint32_t*)(g_wplo + o + 2) = l1;
}

// ------------------------------ GEMM kernels --------------------------------
// proj: block 128x256, 8 warps (2m x 4n), warp 64x64
__global__ __launch_bounds__(256) void proj_gemm() {
  extern __shared__ char sm[];
  int t = threadIdx.x, w = t >> 5, lane = t & 31;
  int z = blockIdx.z, p = z >> 2, b = z & 3;
  int m0 = blockIdx.y * 128, n0 = blockIdx.x * 256;
  int h0 = n0 >> 6;

  const __nv_bfloat16* Ah_g = g_xhi + ((size_t)p * 4 + b) * SQ * D + (size_t)m0 * D;
  const __nv_bfloat16* Al_g = g_xlo + ((size_t)p * 4 + b) * SQ * D + (size_t)m0 * D;
  const __nv_bfloat16* Bh_g = g_wthi + (size_t)p * 1024 * 1024 + (size_t)n0 * 1024;
  const __nv_bfloat16* Bl_g = g_wtlo + (size_t)p * 1024 * 1024 + (size_t)n0 * 1024;

  uint32_t sb0 = cvta_s(sm);
  int wm = w & 1, wn = w >> 1;
  float acc[4][8][4] = {};

  const int NCH = D / KC;  // 16
  {
    uint32_t s = sb0;
    fillT<128, 256>(s,                 Ah_g, D,    t);
    fillT<128, 256>(s + TBA,           Al_g, D,    t);
    fillT<256, 256>(s + 2 * TBA,        Bh_g, 1024, t);
    fillT<256, 256>(s + 2 * TBA + TBA2, Bl_g, 1024, t);
    cp_commit();
  }
  for (int c = 0; c < NCH; ++c) {
    if (c + 1 < NCH) {
      uint32_t s = sb0 + ((c + 1) & 1) * STAGE_P;
      int k0 = (c + 1) * KC;
      fillT<128, 256>(s,                 Ah_g + k0, D,    t);
      fillT<128, 256>(s + TBA,           Al_g + k0, D,    t);
      fillT<256, 256>(s + 2 * TBA,        Bh_g + k0, 1024, t);
      fillT<256, 256>(s + 2 * TBA + TBA2, Bl_g + k0, 1024, t);
      cp_commit();
      cp_wait1();
    } else {
      cp_wait0();
    }
    __syncthreads();
    uint32_t s = sb0 + (c & 1) * STAGE_P;
    mma_tile_w<4, 4>(acc, s, s + TBA, s + 2 * TBA, s + 2 * TBA + TBA2,
                     wm * 64, wn * 64);
    __syncthreads();
  }

  int g = lane >> 2, tq = (lane & 3) * 2;
  if (p < 2) {
    __nv_bfloat16* Hi = (p == 0) ? g_qhi : g_khi;
    __nv_bfloat16* Lo = (p == 0) ? g_qlo : g_klo;
    #pragma unroll
    for (int mi = 0; mi < 4; ++mi)
      #pragma unroll
      for (int nj = 0; nj < 8; ++nj) {
        int row = m0 + wm * 64 + mi * 16 + g;
        int col = n0 + wn * 64 + nj * 8 + tq;
        int h = col >> 6, kc = col & 63;
        size_t o0 = ((size_t)(b * H + h) * 1024 + row) * 64 + kc;
        size_t o1 = ((size_t)(b * H + h) * 1024 + row + 8) * 64 + kc;
        uint32_t hv, lv;
        split_pack(acc[mi][nj][0], acc[mi][nj][1], hv, lv);
        *(uint32_t*)(Hi + o0) = hv; *(uint32_t*)(Lo + o0) = lv;
        split_pack(acc[mi][nj][2], acc[mi][nj][3], hv, lv);
        *(uint32_t*)(Hi + o1) = hv; *(uint32_t*)(Lo + o1) = lv;
      }
  } else {
    // V: write transposed [bh][v][s]
    #pragma unroll
    for (int mi = 0; mi < 4; ++mi)
      #pragma unroll
      for (int nj = 0; nj < 8; ++nj) {
        int row = m0 + wm * 64 + mi * 16 + g;
        int col = n0 + wn * 64 + nj * 8 + tq;
        int h = col >> 6, kc = col & 63;
        size_t base = (size_t)(b * H + h) * 64 * 1024;
        #pragma unroll
        for (int j = 0; j < 4; ++j) {
          int v = kc + (j & 1);
          int srow = row + (j >> 1) * 8;
          float x = acc[mi][nj][j];
          __nv_bfloat16 hb = __float2bfloat16(x);
          g_vthi[base + (size_t)v * 1024 + srow] = hb;
          g_vtlo[base + (size_t)v * 1024 + srow] =
              __float2bfloat16(x - __bfloat162float(hb));
        }
      }
  }
}

// scores: block 128x256, single K chunk
__global__ __launch_bounds__(256) void scores_gemm(float* __restrict__ attns) {
  extern __shared__ char sm[];
  int t = threadIdx.x, w = t >> 5, lane = t & 31;
  int z = blockIdx.z, b = z >> 4, h = z & 15;
  int m0 = blockIdx.y * 128, n0 = blockIdx.x * 256;

  const __nv_bfloat16* Ah_g = g_qhi + (size_t)z * 1024 * 64 + (size_t)m0 * 64;
  const __nv_bfloat16* Al_g = g_qlo + (size_t)z * 1024 * 64 + (size_t)m0 * 64;
  const __nv_bfloat16* Bh_g = g_khi + (size_t)z * 1024 * 64 + (size_t)n0 * 64;
  const __nv_bfloat16* Bl_g = g_klo + (size_t)z * 1024 * 64 + (size_t)n0 * 64;

  uint32_t s = cvta_s(sm);
  fillT<128, 256>(s,                 Ah_g, 64, t);
  fillT<128, 256>(s + TBA,           Al_g, 64, t);
  fillT<256, 256>(s + 2 * TBA,        Bh_g, 64, t);
  fillT<256, 256>(s + 2 * TBA + TBA2, Bl_g, 64, t);
  cp_commit();
  cp_wait0();
  __syncthreads();

  int wm = w & 1, wn = w >> 1;
  float acc[4][8][4] = {};
  mma_tile_w<4, 4>(acc, s, s + TBA, s + 2 * TBA, s + 2 * TBA + TBA2,
                   wm * 64, wn * 64);

  int g = lane >> 2, tq = (lane & 3) * 2;
  float* outb = attns + (size_t)(h * B + b) * SQ * SK;
  #pragma unroll
  for (int mi = 0; mi < 4; ++mi)
    #pragma unroll
    for (int nj = 0; nj < 8; ++nj) {
      int row = m0 + wm * 64 + mi * 16 + g;
      int col = n0 + wn * 64 + nj * 8 + tq;
      *reinterpret_cast<float2*>(&outb[(size_t)row * SK + col]) =
          make_float2(acc[mi][nj][0] * INV_SCALE, acc[mi][nj][1] * INV_SCALE);
      *reinterpret_cast<float2*>(&outb[(size_t)(row + 8) * SK + col]) =
          make_float2(acc[mi][nj][2] * INV_SCALE, acc[mi][nj][3] * INV_SCALE);
    }
}

__global__ __launch_bounds__(256) void softmax_kernel(float* __restrict__ attns) {
  __shared__ float redm[8];
  __shared__ float reds[8];
  size_t rb = (size_t)blockIdx.x * SK;
  float* p = attns + rb;
  int tid = threadIdx.x;

  float4 v = reinterpret_cast<float4*>(p)[tid];
  float mx = fmaxf(fmaxf(v.x, v.y), fmaxf(v.z, v.w));
  #pragma unroll
  for (int o = 16; o > 0; o >>= 1) mx = fmaxf(mx, __shfl_xor_sync(0xffffffffu, mx, o));
  if ((tid & 31) == 0) redm[tid >> 5] = mx;
  __syncthreads();
  float m_all = redm[0];
  #pragma unroll
  for (int i = 1; i < 8; ++i) m_all = fmaxf(m_all, redm[i]);

  v.x = __expf(v.x - m_all); v.y = __expf(v.y - m_all);
  v.z = __expf(v.z - m_all); v.w = __expf(v.w - m_all);
  float s = v.x + v.y + v.z + v.w;
  #pragma unroll
  for (int o = 16; o > 0; o >>= 1) s += __shfl_xor_sync(0xffffffffu, s, o);
  if ((tid & 31) == 0) reds[tid >> 5] = s;
  __syncthreads();
  float s_all = 0.f;
  #pragma unroll
  for (int i = 0; i < 8; ++i) s_all += reds[i];
  float inv = 1.0f / s_all;

  v.x *= inv; v.y *= inv; v.z *= inv; v.w *= inv;
  reinterpret_cast<float4*>(p)[tid] = v;

  uint32_t h0, l0, h1, l1;
  split_pack(v.x, v.y, h0, l0);
  split_pack(v.z, v.w, h1, l1);
  size_t o = rb + (size_t)tid * 4;
  *(uint32_t*)(g_phi + o)     = h0;  *(uint32_t*)(g_phi + o + 2) = h1;
  *(uint32_t*)(g_plo + o)     = l0;  *(uint32_t*)(g_plo + o + 2) = l1;
}

// av: block 256x64, 4 warps (4m x 1n), warp 64x64, 128 threads
__global__ __launch_bounds__(128) void av_gemm() {
  extern __shared__ char sm[];
  int t = threadIdx.x, w = t >> 5, lane = t & 31;
  int z = blockIdx.z, b = z >> 4, h = z & 15;
  int m0 = blockIdx.y * 256;

  const __nv_bfloat16* Ah_g = g_phi + (size_t)(h * B + b) * SQ * SK + (size_t)m0 * SK;
  const __nv_bfloat16* Al_g = g_plo + (size_t)(h * B + b) * SQ * SK + (size_t)m0 * SK;
  const __nv_bfloat16* Bh_g = g_vthi + (size_t)z * 64 * 1024;
  const __nv_bfloat16* Bl_g = g_vtlo + (size_t)z * 64 * 1024;

  uint32_t sb0 = cvta_s(sm);
  float acc[4][8][4] = {};

  const int NCH = SK / KC;  // 16
  {
    uint32_t s = sb0;
    fillT<256, 128>(s,                   Ah_g, 1024, t);
    fillT<256, 128>(s + TBA2,            Al_g, 1024, t);
    fillT<64, 128> (s + 2 * TBA2,         Bh_g, 1024, t);
    fillT<64, 128> (s + 2 * TBA2 + TBB64, Bl_g, 1024, t);
    cp_commit();
  }
  for (int c = 0; c < NCH; ++c) {
    if (c + 1 < NCH) {
      uint32_t s = sb0 + ((c + 1) & 1) * STAGE_AV;
      int k0 = (c + 1) * KC;
      fillT<256, 128>(s,                   Ah_g + k0, 1024, t);
      fillT<256, 128>(s + TBA2,            Al_g + k0, 1024, t);
      fillT<64, 128> (s + 2 * TBA2,         Bh_g + k0, 1024, t);
      fillT<64, 128> (s + 2 * TBA2 + TBB64, Bl_g + k0, 1024, t);
      cp_commit();
      cp_wait1();
    } else {
      cp_wait0();
    }
    __syncthreads();
    uint32_t s = sb0 + (c & 1) * STAGE_AV;
    mma_tile_w<4, 4>(acc, s, s + TBA2, s + 2 * TBA2, s + 2 * TBA2 + TBB64,
                     w * 64, 0);
    __syncthreads();
  }

  int g = lane >> 2, tq = (lane & 3) * 2;
  #pragma unroll
  for (int mi = 0; mi < 4; ++mi)
    #pragma unroll
    for (int nj = 0; nj < 8; ++nj) {
      int row = m0 + w * 64 + mi * 16 + g;
      int col = nj * 8 + tq;
      size_t o0 = ((size_t)b * 1024 + row) * 1024 + h * 64 + col;
      size_t o1 = ((size_t)b * 1024 + row + 8) * 1024 + h * 64 + col;
      uint32_t hv, lv;
      split_pack(acc[mi][nj][0], acc[mi][nj][1], hv, lv);
      *(uint32_t*)(g_ctxhi + o0) = hv; *(uint32_t*)(g_ctxlo + o0) = lv;
      split_pack(acc[mi][nj][2], acc[mi][nj][3], hv, lv);
      *(uint32_t*)(g_ctxhi + o1) = hv; *(uint32_t*)(g_ctxlo + o1) = lv;
    }
}

// outproj: block 128x256
__global__ __launch_bounds__(256) void outproj_gemm(const float* __restrict__ b_proj,
                                                    float* __restrict__ out) {
  extern __shared__ char sm[];
  int t = threadIdx.x, w = t >> 5, lane = t & 31;
  int m0 = blockIdx.y * 128, n0 = blockIdx.x * 256;

  const __nv_bfloat16* Ah_g = g_ctxhi + (size_t)m0 * 1024;
  const __nv_bfloat16* Al_g = g_ctxlo + (size_t)m0 * 1024;
  const __nv_bfloat16* Bh_g = g_wphi + (size_t)n0 * 1024;
  const __nv_bfloat16* Bl_g = g_wplo + (size_t)n0 * 1024;

  uint32_t sb0 = cvta_s(sm);
  int wm = w & 1, wn = w >> 1;
  float acc[4][8][4] = {};

  const int NCH = 1024 / KC;  // 16
  {
    uint32_t s = sb0;
    fillT<128, 256>(s,                 Ah_g, 1024, t);
    fillT<128, 256>(s + TBA,           Al_g, 1024, t);
    fillT<256, 256>(s + 2 * TBA,        Bh_g, 1024, t);
    fillT<256, 256>(s + 2 * TBA + TBA2, Bl_g, 1024, t);
    cp_commit();
  }
  for (int c = 0; c < NCH; ++c) {
    if (c + 1 < NCH) {
      uint32_t s = sb0 + ((c + 1) & 1) * STAGE_P;
      int k0 = (c + 1) * KC;
      fillT<128, 256>(s,                 Ah_g + k0, 1024, t);
      fillT<128, 256>(s + TBA,           Al_g + k0, 1024, t);
      fillT<256, 256>(s + 2 * TBA,        Bh_g + k0, 1024, t);
      fillT<256, 256>(s + 2 * TBA + TBA2, Bl_g + k0, 1024, t);
      cp_commit();
      cp_wait1();
    } else {
      cp_wait0();
    }
    __syncthreads();
    uint32_t s = sb0 + (c & 1) * STAGE_P;
    mma_tile_w<4, 4>(acc, s, s + TBA, s + 2 * TBA, s + 2 * TBA + TBA2,
                     wm * 64, wn * 64);
    __syncthreads();
  }

  int g = lane >> 2, tq = (lane & 3) * 2;
  #pragma unroll
  for (int mi = 0; mi < 4; ++mi)
    #pragma unroll
    for (int nj = 0; nj < 8; ++nj) {
      int row = m0 + wm * 64 + mi * 16 + g;
      int col = n0 + wn * 64 + nj * 8 + tq;
      float2 bb = *reinterpret_cast<const float2*>(&b_proj[col]);
      *reinterpret_cast<float2*>(&out[(size_t)row * D + col]) =
          make_float2(acc[mi][nj][0] + bb.x, acc[mi][nj][1] + bb.y);
      *reinterpret_cast<float2*>(&out[(size_t)(row + 8) * D + col]) =
          make_float2(acc[mi][nj][2] + bb.x, acc[mi][nj][3] + bb.y);
    }
}

// ---------------------------------------------------------------------------
extern "C" void kernel_launch(void* const* d_in, const int* in_sizes, int n_in,
                              void* d_out, int out_size) {
  const float* query  = (const float*)d_in[0];
  const float* key    = (const float*)d_in[1];
  const float* value  = (const float*)d_in[2];
  const float* w_q    = (const float*)d_in[3];
  const float* w_k    = (const float*)d_in[4];
  const float* w_v    = (const float*)d_in[5];
  const float* w_proj = (const float*)d_in[6];
  const float* b_proj = (const float*)d_in[7];

  float* out   = (float*)d_out;
  float* attns = out + (size_t)B * SQ * D;

  static bool attr_done = false;
  if (!attr_done) {
    cudaFuncSetAttribute(proj_gemm,    cudaFuncAttributeMaxDynamicSharedMemorySize, SMEM_P2);
    cudaFuncSetAttribute(scores_gemm,  cudaFuncAttributeMaxDynamicSharedMemorySize, SMEM_SC1);
    cudaFuncSetAttribute(av_gemm,      cudaFuncAttributeMaxDynamicSharedMemorySize, SMEM_AV2);
    cudaFuncSetAttribute(outproj_gemm, cudaFuncAttributeMaxDynamicSharedMemorySize, SMEM_P2);
    attr_done = true;
  }

  conv_x <<<dim3(4096, 3), 256>>>(query, key, value);
  conv_w <<<dim3(1024, 3), 256>>>(w_q, w_k, w_v);
  conv_wp<<<dim3(1024, 1), 256>>>(w_proj);

  proj_gemm   <<<dim3(4, 8, 12), 256, SMEM_P2>>>();
  scores_gemm <<<dim3(4, 8, 64), 256, SMEM_SC1>>>(attns);
  softmax_kernel<<<H * B * SQ, 256>>>(attns);
  av_gemm     <<<dim3(1, 4, 64), 128, SMEM_AV2>>>();
  outproj_gemm<<<dim3(4, 32, 1), 256, SMEM_P2>>>(b_proj, out);
}

// round 13
// speedup vs baseline: 1.1376x; 1.1376x over previous
#include <cuda_runtime.h>
#include <cuda_bf16.h>
#include <cstdint>

namespace {
constexpr int H  = 16;
constexpr int D  = 1024;
constexpr int B  = 4;
constexpr int SQ = 1024;
constexpr int SK = 1024;
constexpr float INV_SCALE = 1.0f / 32.0f;

constexpr int KC    = 64;                    // K-chunk
constexpr int KSE   = 72;                    // smem row stride (elems); conflict-free ldmatrix
constexpr int TBA   = 128 * KSE * 2;         // 18432 B (128-row tile)
constexpr int TBA2  = 256 * KSE * 2;         // 36864 B (256-row tile)
constexpr int TBB64 = 64 * KSE * 2;          // 9216 B  (64-row tile)
constexpr int STAGE_BIG = 4 * TBA;           // 73728
constexpr int SMEM_PIPE = 2 * STAGE_BIG;     // 147456
constexpr int SMEM_SC   = STAGE_BIG;         // scores: single stage
constexpr int STAGE_AV  = 2 * TBA2 + 2 * TBB64;  // 92160
constexpr int SMEM_AV   = 2 * STAGE_AV;      // 184320
}

// ------------------------- global scratch (bf16 hi/lo) ----------------------
__device__ __nv_bfloat16 g_xhi[3u * 4 * 1024 * 1024];
__device__ __nv_bfloat16 g_xlo[3u * 4 * 1024 * 1024];
__device__ __nv_bfloat16 g_wthi[3u * 1024 * 1024];   // [p][n=h*64+c][d]
__device__ __nv_bfloat16 g_wtlo[3u * 1024 * 1024];
__device__ __nv_bfloat16 g_qhi[64u * 1024 * 64];     // [bh][s][k]
__device__ __nv_bfloat16 g_qlo[64u * 1024 * 64];
__device__ __nv_bfloat16 g_khi[64u * 1024 * 64];
__device__ __nv_bfloat16 g_klo[64u * 1024 * 64];
__device__ __nv_bfloat16 g_vthi[64u * 64 * 1024];    // [bh][v][s]
__device__ __nv_bfloat16 g_vtlo[64u * 64 * 1024];
__device__ __nv_bfloat16 g_phi[64u * 1024 * 1024];   // [h*B+b][q][s]
__device__ __nv_bfloat16 g_plo[64u * 1024 * 1024];
__device__ __nv_bfloat16 g_ctxhi[4096u * 1024];      // [b*q][h*64+v]
__device__ __nv_bfloat16 g_ctxlo[4096u * 1024];
__device__ __nv_bfloat16 g_wphi[1024u * 1024];       // [n][k]
__device__ __nv_bfloat16 g_wplo[1024u * 1024];

// ------------------------------ helpers -------------------------------------
__device__ __forceinline__ uint32_t cvta_s(const void* p) {
  uint32_t a;
  asm("{ .reg .u64 t; cvta.to.shared.u64 t, %1; cvt.u32.u64 %0, t; }" : "=r"(a) : "l"(p));
  return a;
}
__device__ __forceinline__ void cp16(uint32_t d, const void* s) {
  asm volatile("cp.async.ca.shared.global [%0], [%1], 16;" :: "r"(d), "l"(s));
}
__device__ __forceinline__ void cp_commit() { asm volatile("cp.async.commit_group;" ::: "memory"); }
__device__ __forceinline__ void cp_wait0()  { asm volatile("cp.async.wait_group 0;" ::: "memory"); }
__device__ __forceinline__ void cp_wait1()  { asm volatile("cp.async.wait_group 1;" ::: "memory"); }

__device__ __forceinline__ void ldm4(uint32_t& r0, uint32_t& r1, uint32_t& r2, uint32_t& r3,
                                     uint32_t a) {
  asm volatile("ldmatrix.sync.aligned.m8n8.x4.shared.b16 {%0,%1,%2,%3}, [%4];"
               : "=r"(r0), "=r"(r1), "=r"(r2), "=r"(r3) : "r"(a));
}
// NOTE: not volatile — pure register op; still ordered per-accumulator by data deps.
__device__ __forceinline__ void mma_bf16(float* c, const uint32_t* a, uint32_t b0, uint32_t b1) {
  asm("mma.sync.aligned.m16n8k16.row.col.f32.bf16.bf16.f32 "
      "{%0,%1,%2,%3}, {%4,%5,%6,%7}, {%8,%9}, {%0,%1,%2,%3};"
      : "+f"(c[0]), "+f"(c[1]), "+f"(c[2]), "+f"(c[3])
      : "r"(a[0]), "r"(a[1]), "r"(a[2]), "r"(a[3]), "r"(b0), "r"(b1));
}

__device__ __forceinline__ void split_pack(float a, float b, uint32_t& hi, uint32_t& lo) {
  __nv_bfloat16 h0 = __float2bfloat16(a), h1 = __float2bfloat16(b);
  __nv_bfloat16 l0 = __float2bfloat16(a - __bfloat162float(h0));
  __nv_bfloat16 l1 = __float2bfloat16(b - __bfloat162float(h1));
  hi = (uint32_t)__bfloat16_as_ushort(h0) | ((uint32_t)__bfloat16_as_ushort(h1) << 16);
  lo = (uint32_t)__bfloat16_as_ushort(l0) | ((uint32_t)__bfloat16_as_ushort(l1) << 16);
}

// fill ROWS x 64-k tile via cp.async with NT threads
template <int ROWS, int NT>
__device__ __forceinline__ void fillT(uint32_t sbase, const __nv_bfloat16* g,
                                      int rstride, int t) {
  #pragma unroll
  for (int i = 0; i < ROWS * 8 / NT; ++i) {
    int f = t + i * NT;
    int r = f >> 3, ck = (f & 7) * 8;
    cp16(sbase + (uint32_t)(r * KSE + ck) * 2, g + (size_t)r * rstride + ck);
  }
}

// split 3-term MMA over one 64-k chunk, TERM-MAJOR issue order:
// pass1 all hi*hi, pass2 all lo*hi, pass3 all hi*lo — dependent MMAs to the
// same accumulator are separated by 2*MI*NI independent ones.
template <int MI>
__device__ __forceinline__ void mma_tile(float (*acc)[4][4],
                                         uint32_t sAh, uint32_t sAl,
                                         uint32_t sBh, uint32_t sBl,
                                         int arow0, int brow0) {
  int lane = threadIdx.x & 31;
  int lr = lane & 15, lh = lane >> 4;
  #pragma unroll
  for (int ks = 0; ks < KC; ks += 16) {
    int ko = ks + lh * 8;
    uint32_t ah[MI][4], al[MI][4];
    #pragma unroll
    for (int mi = 0; mi < MI; ++mi) {
      uint32_t off = (uint32_t)((arow0 + mi * 16 + lr) * KSE + ko) * 2;
      ldm4(ah[mi][0], ah[mi][1], ah[mi][2], ah[mi][3], sAh + off);
      ldm4(al[mi][0], al[mi][1], al[mi][2], al[mi][3], sAl + off);
    }
    uint32_t bh[2][4], bl[2][4];
    #pragma unroll
    for (int np = 0; np < 2; ++np) {
      uint32_t off = (uint32_t)((brow0 + np * 16 + lr) * KSE + ko) * 2;
      ldm4(bh[np][0], bh[np][1], bh[np][2], bh[np][3], sBh + off);
      ldm4(bl[np][0], bl[np][1], bl[np][2], bl[np][3], sBl + off);
    }
    // pass 1: hi * hi
    #pragma unroll
    for (int mi = 0; mi < MI; ++mi)
      #pragma unroll
      for (int np = 0; np < 2; ++np) {
        mma_bf16(acc[mi][2 * np],     ah[mi], bh[np][0], bh[np][2]);
        mma_bf16(acc[mi][2 * np + 1], ah[mi], bh[np][1], bh[np][3]);
      }
    // pass 2: lo * hi
    #pragma unroll
    for (int mi = 0; mi < MI; ++mi)
      #pragma unroll
      for (int np = 0; np < 2; ++np) {
        mma_bf16(acc[mi][2 * np],     al[mi], bh[np][0], bh[np][2]);
        mma_bf16(acc[mi][2 * np + 1], al[mi], bh[np][1], bh[np][3]);
      }
    // pass 3: hi * lo
    #pragma unroll
    for (int mi = 0; mi < MI; ++mi)
      #pragma unroll
      for (int np = 0; np < 2; ++np) {
        mma_bf16(acc[mi][2 * np],     ah[mi], bl[np][0], bl[np][2]);
        mma_bf16(acc[mi][2 * np + 1], ah[mi], bl[np][1], bl[np][3]);
      }
  }
}

// -------------------------- pre-pass conversions ----------------------------
__global__ __launch_bounds__(256) void conv_x(const float* __restrict__ query,
                                              const float* __restrict__ key,
                                              const float* __restrict__ value) {
  int p = blockIdx.y;
  const float* src = (p == 0) ? query : (p == 1) ? key : value;
  size_t i = ((size_t)blockIdx.x * 256 + threadIdx.x) * 4;
  float4 v = *reinterpret_cast<const float4*>(src + i);
  size_t o = (size_t)p * 4 * 1024 * 1024 + i;
  uint32_t h0, l0, h1, l1;
  split_pack(v.x, v.y, h0, l0);
  split_pack(v.z, v.w, h1, l1);
  *(uint32_t*)(g_xhi + o)     = h0;  *(uint32_t*)(g_xhi + o + 2) = h1;
  *(uint32_t*)(g_xlo + o)     = l0;  *(uint32_t*)(g_xlo + o + 2) = l1;
}

__global__ __launch_bounds__(256) void conv_w(const float* __restrict__ w_q,
                                              const float* __restrict__ w_k,
                                              const float* __restrict__ w_v) {
  int p = blockIdx.y, n = blockIdx.x;
  const float* W = (p == 0) ? w_q : (p == 1) ? w_k : w_v;
  int h = n >> 6, c = n & 63;
  int d0 = threadIdx.x * 4;
  float a = W[(size_t)h * 65536 + (size_t)(d0 + 0) * 64 + c];
  float b = W[(size_t)h * 65536 + (size_t)(d0 + 1) * 64 + c];
  float e = W[(size_t)h * 65536 + (size_t)(d0 + 2) * 64 + c];
  float f = W[(size_t)h * 65536 + (size_t)(d0 + 3) * 64 + c];
  size_t o = ((size_t)p * 1024 + n) * 1024 + d0;
  uint32_t h0, l0, h1, l1;
  split_pack(a, b, h0, l0);
  split_pack(e, f, h1, l1);
  *(uint32_t*)(g_wthi + o)     = h0;  *(uint32_t*)(g_wthi + o + 2) = h1;
  *(uint32_t*)(g_wtlo + o)     = l0;  *(uint32_t*)(g_wtlo + o + 2) = l1;
}

__global__ __launch_bounds__(256) void conv_wp(const float* __restrict__ w_proj) {
  int n = blockIdx.x;
  int k0 = threadIdx.x * 4;
  float4 v = *reinterpret_cast<const float4*>(w_proj + (size_t)n * 1024 + k0);
  size_t o = (size_t)n * 1024 + k0;
  uint32_t h0, l0, h1, l1;
  split_pack(v.x, v.y, h0, l0);
  split_pack(v.z, v.w, h1, l1);
  *(uint32_t*)(g_wphi + o)     = h0;  *(uint32_t*)(g_wphi + o + 2) = h1;
  *(uint32_t*)(g_wplo + o)     = l0;  *(uint32_t*)(g_wplo + o + 2) = l1;
}

// ------------------------------ GEMM kernels --------------------------------
__global__ __launch_bounds__(256) void proj_gemm() {
  extern __shared__ char sm[];
  int t = threadIdx.x, w = t >> 5, lane = t & 31;
  int z = blockIdx.z, p = z >> 2, b = z & 3;
  int m0 = blockIdx.y * 128, n0 = blockIdx.x * 128;

  const __nv_bfloat16* Ah_g = g_xhi + ((size_t)p * 4 + b) * SQ * D + (size_t)m0 * D;
  const __nv_bfloat16* Al_g = g_xlo + ((size_t)p * 4 + b) * SQ * D + (size_t)m0 * D;
  const __nv_bfloat16* Bh_g = g_wthi + (size_t)p * 1024 * 1024 + (size_t)n0 * 1024;
  const __nv_bfloat16* Bl_g = g_wtlo + (size_t)p * 1024 * 1024 + (size_t)n0 * 1024;

  uint32_t sb0 = cvta_s(sm);
  int wm = w & 1, wn = w >> 1;
  float acc[4][4][4] = {};

  const int NCH = D / KC;  // 16
  {
    uint32_t s = sb0;
    fillT<128, 256>(s,           Ah_g, D,    t);
    fillT<128, 256>(s + TBA,     Al_g, D,    t);
    fillT<128, 256>(s + 2 * TBA, Bh_g, 1024, t);
    fillT<128, 256>(s + 3 * TBA, Bl_g, 1024, t);
    cp_commit();
  }
  for (int c = 0; c < NCH; ++c) {
    if (c + 1 < NCH) {
      uint32_t s = sb0 + ((c + 1) & 1) * STAGE_BIG;
      int k0 = (c + 1) * KC;
      fillT<128, 256>(s,           Ah_g + k0, D,    t);
      fillT<128, 256>(s + TBA,     Al_g + k0, D,    t);
      fillT<128, 256>(s + 2 * TBA, Bh_g + k0, 1024, t);
      fillT<128, 256>(s + 3 * TBA, Bl_g + k0, 1024, t);
      cp_commit();
      cp_wait1();
    } else {
      cp_wait0();
    }
    __syncthreads();
    uint32_t s = sb0 + (c & 1) * STAGE_BIG;
    mma_tile<4>(acc, s, s + TBA, s + 2 * TBA, s + 3 * TBA, wm * 64, wn * 32);
    __syncthreads();
  }

  int g = lane >> 2, tq = (lane & 3) * 2;
  if (p < 2) {
    __nv_bfloat16* Hi = (p == 0) ? g_qhi : g_khi;
    __nv_bfloat16* Lo = (p == 0) ? g_qlo : g_klo;
    #pragma unroll
    for (int mi = 0; mi < 4; ++mi)
      #pragma unroll
      for (int ni = 0; ni < 4; ++ni) {
        int row = m0 + wm * 64 + mi * 16 + g;
        int col = n0 + wn * 32 + ni * 8 + tq;
        int h = col >> 6, kc = col & 63;
        size_t o0 = ((size_t)(b * H + h) * 1024 + row) * 64 + kc;
        size_t o1 = ((size_t)(b * H + h) * 1024 + row + 8) * 64 + kc;
        uint32_t hv, lv;
        split_pack(acc[mi][ni][0], acc[mi][ni][1], hv, lv);
        *(uint32_t*)(Hi + o0) = hv; *(uint32_t*)(Lo + o0) = lv;
        split_pack(acc[mi][ni][2], acc[mi][ni][3], hv, lv);
        *(uint32_t*)(Hi + o1) = hv; *(uint32_t*)(Lo + o1) = lv;
      }
  } else {
    // V: write transposed [bh][v][s]
    #pragma unroll
    for (int mi = 0; mi < 4; ++mi)
      #pragma unroll
      for (int ni = 0; ni < 4; ++ni) {
        int row = m0 + wm * 64 + mi * 16 + g;
        int col = n0 + wn * 32 + ni * 8 + tq;
        int h = col >> 6, kc = col & 63;
        size_t base = (size_t)(b * H + h) * 64 * 1024;
        #pragma unroll
        for (int j = 0; j < 4; ++j) {
          int v = kc + (j & 1);
          int srow = row + (j >> 1) * 8;
          float x = acc[mi][ni][j];
          __nv_bfloat16 hb = __float2bfloat16(x);
          g_vthi[base + (size_t)v * 1024 + srow] = hb;
          g_vtlo[base + (size_t)v * 1024 + srow] =
              __float2bfloat16(x - __bfloat162float(hb));
        }
      }
  }
}

__global__ __launch_bounds__(256) void scores_gemm(float* __restrict__ attns) {
  extern __shared__ char sm[];
  int t = threadIdx.x, w = t >> 5, lane = t & 31;
  int z = blockIdx.z, b = z >> 4, h = z & 15;
  int m0 = blockIdx.y * 128, n0 = blockIdx.x * 128;

  const __nv_bfloat16* Ah_g = g_qhi + (size_t)z * 1024 * 64 + (size_t)m0 * 64;
  const __nv_bfloat16* Al_g = g_qlo + (size_t)z * 1024 * 64 + (size_t)m0 * 64;
  const __nv_bfloat16* Bh_g = g_khi + (size_t)z * 1024 * 64 + (size_t)n0 * 64;
  const __nv_bfloat16* Bl_g = g_klo + (size_t)z * 1024 * 64 + (size_t)n0 * 64;

  uint32_t s = cvta_s(sm);
  fillT<128, 256>(s,           Ah_g, 64, t);
  fillT<128, 256>(s + TBA,     Al_g, 64, t);
  fillT<128, 256>(s + 2 * TBA, Bh_g, 64, t);
  fillT<128, 256>(s + 3 * TBA, Bl_g, 64, t);
  cp_commit();
  cp_wait0();
  __syncthreads();

  int wm = w & 1, wn = w >> 1;
  float acc[4][4][4] = {};
  mma_tile<4>(acc, s, s + TBA, s + 2 * TBA, s + 3 * TBA, wm * 64, wn * 32);

  int g = lane >> 2, tq = (lane & 3) * 2;
  float* outb = attns + (size_t)(h * B + b) * SQ * SK;
  #pragma unroll
  for (int mi = 0; mi < 4; ++mi)
    #pragma unroll
    for (int ni = 0; ni < 4; ++ni) {
      int row = m0 + wm * 64 + mi * 16 + g;
      int col = n0 + wn * 32 + ni * 8 + tq;
      *reinterpret_cast<float2*>(&outb[(size_t)row * SK + col]) =
          make_float2(acc[mi][ni][0] * INV_SCALE, acc[mi][ni][1] * INV_SCALE);
      *reinterpret_cast<float2*>(&outb[(size_t)(row + 8) * SK + col]) =
          make_float2(acc[mi][ni][2] * INV_SCALE, acc[mi][ni][3] * INV_SCALE);
    }
}

__global__ __launch_bounds__(256) void softmax_kernel(float* __restrict__ attns) {
  __shared__ float redm[8];
  __shared__ float reds[8];
  size_t rb = (size_t)blockIdx.x * SK;
  float* p = attns + rb;
  int tid = threadIdx.x;

  float4 v = reinterpret_cast<float4*>(p)[tid];
  float mx = fmaxf(fmaxf(v.x, v.y), fmaxf(v.z, v.w));
  #pragma unroll
  for (int o = 16; o > 0; o >>= 1) mx = fmaxf(mx, __shfl_xor_sync(0xffffffffu, mx, o));
  if ((tid & 31) == 0) redm[tid >> 5] = mx;
  __syncthreads();
  float m_all = redm[0];
  #pragma unroll
  for (int i = 1; i < 8; ++i) m_all = fmaxf(m_all, redm[i]);

  v.x = __expf(v.x - m_all); v.y = __expf(v.y - m_all);
  v.z = __expf(v.z - m_all); v.w = __expf(v.w - m_all);
  float s = v.x + v.y + v.z + v.w;
  #pragma unroll
  for (int o = 16; o > 0; o >>= 1) s += __shfl_xor_sync(0xffffffffu, s, o);
  if ((tid & 31) == 0) reds[tid >> 5] = s;
  __syncthreads();
  float s_all = 0.f;
  #pragma unroll
  for (int i = 0; i < 8; ++i) s_all += reds[i];
  float inv = 1.0f / s_all;

  v.x *= inv; v.y *= inv; v.z *= inv; v.w *= inv;
  reinterpret_cast<float4*>(p)[tid] = v;

  uint32_t h0, l0, h1, l1;
  split_pack(v.x, v.y, h0, l0);
  split_pack(v.z, v.w, h1, l1);
  size_t o = rb + (size_t)tid * 4;
  *(uint32_t*)(g_phi + o)     = h0;  *(uint32_t*)(g_phi + o + 2) = h1;
  *(uint32_t*)(g_plo + o)     = l0;  *(uint32_t*)(g_plo + o + 2) = l1;
}

// av: 256x64 block tile, 8 warps = 4m x 2n, warp tile 64x32, MI=4
__global__ __launch_bounds__(256) void av_gemm() {
  extern __shared__ char sm[];
  int t = threadIdx.x, w = t >> 5, lane = t & 31;
  int z = blockIdx.z, b = z >> 4, h = z & 15;
  int m0 = blockIdx.y * 256;

  const __nv_bfloat16* Ah_g = g_phi + (size_t)(h * B + b) * SQ * SK + (size_t)m0 * SK;
  const __nv_bfloat16* Al_g = g_plo + (size_t)(h * B + b) * SQ * SK + (size_t)m0 * SK;
  const __nv_bfloat16* Bh_g = g_vthi + (size_t)z * 64 * 1024;
  const __nv_bfloat16* Bl_g = g_vtlo + (size_t)z * 64 * 1024;

  uint32_t sb0 = cvta_s(sm);
  int wm = w & 3, wn = w >> 2;
  float acc[4][4][4] = {};

  const int NCH = SK / KC;  // 16
  {
    uint32_t s = sb0;
    fillT<256, 256>(s,                   Ah_g, 1024, t);
    fillT<256, 256>(s + TBA2,            Al_g, 1024, t);
    fillT<64, 256> (s + 2 * TBA2,         Bh_g, 1024, t);
    fillT<64, 256> (s + 2 * TBA2 + TBB64, Bl_g, 1024, t);
    cp_commit();
  }
  for (int c = 0; c < NCH; ++c) {
    if (c + 1 < NCH) {
      uint32_t s = sb0 + ((c + 1) & 1) * STAGE_AV;
      int k0 = (c + 1) * KC;
      fillT<256, 256>(s,                   Ah_g + k0, 1024, t);
      fillT<256, 256>(s + TBA2,            Al_g + k0, 1024, t);
      fillT<64, 256> (s + 2 * TBA2,         Bh_g + k0, 1024, t);
      fillT<64, 256> (s + 2 * TBA2 + TBB64, Bl_g + k0, 1024, t);
      cp_commit();
      cp_wait1();
    } else {
      cp_wait0();
    }
    __syncthreads();
    uint32_t s = sb0 + (c & 1) * STAGE_AV;
    mma_tile<4>(acc, s, s + TBA2, s + 2 * TBA2, s + 2 * TBA2 + TBB64,
                wm * 64, wn * 32);
    __syncthreads();
  }

  int g = lane >> 2, tq = (lane & 3) * 2;
  #pragma unroll
  for (int mi = 0; mi < 4; ++mi)
    #pragma unroll
    for (int ni = 0; ni < 4; ++ni) {
      int row = m0 + wm * 64 + mi * 16 + g;
      int col = wn * 32 + ni * 8 + tq;
      size_t o0 = ((size_t)b * 1024 + row) * 1024 + h * 64 + col;
      size_t o1 = ((size_t)b * 1024 + row + 8) * 1024 + h * 64 + col;
      uint32_t hv, lv;
      split_pack(acc[mi][ni][0], acc[mi][ni][1], hv, lv);
      *(uint32_t*)(g_ctxhi + o0) = hv; *(uint32_t*)(g_ctxlo + o0) = lv;
      split_pack(acc[mi][ni][2], acc[mi][ni][3], hv, lv);
      *(uint32_t*)(g_ctxhi + o1) = hv; *(uint32_t*)(g_ctxlo + o1) = lv;
    }
}

__global__ __launch_bounds__(256) void outproj_gemm(const float* __restrict__ b_proj,
                                                    float* __restrict__ out) {
  extern __shared__ char sm[];
  int t = threadIdx.x, w = t >> 5, lane = t & 31;
  int m0 = blockIdx.y * 128, n0 = blockIdx.x * 128;

  const __nv_bfloat16* Ah_g = g_ctxhi + (size_t)m0 * 1024;
  const __nv_bfloat16* Al_g = g_ctxlo + (size_t)m0 * 1024;
  const __nv_bfloat16* Bh_g = g_wphi + (size_t)n0 * 1024;
  const __nv_bfloat16* Bl_g = g_wplo + (size_t)n0 * 1024;

  uint32_t sb0 = cvta_s(sm);
  int wm = w & 1, wn = w >> 1;
  float acc[4][4][4] = {};

  const int NCH = 1024 / KC;  // 16
  {
    uint32_t s = sb0;
    fillT<128, 256>(s,           Ah_g, 1024, t);
    fillT<128, 256>(s + TBA,     Al_g, 1024, t);
    fillT<128, 256>(s + 2 * TBA, Bh_g, 1024, t);
    fillT<128, 256>(s + 3 * TBA, Bl_g, 1024, t);
    cp_commit();
  }
  for (int c = 0; c < NCH; ++c) {
    if (c + 1 < NCH) {
      uint32_t s = sb0 + ((c + 1) & 1) * STAGE_BIG;
      int k0 = (c + 1) * KC;
      fillT<128, 256>(s,           Ah_g + k0, 1024, t);
      fillT<128, 256>(s + TBA,     Al_g + k0, 1024, t);
      fillT<128, 256>(s + 2 * TBA, Bh_g + k0, 1024, t);
      fillT<128, 256>(s + 3 * TBA, Bl_g + k0, 1024, t);
      cp_commit();
      cp_wait1();
    } else {
      cp_wait0();
    }
    __syncthreads();
    uint32_t s = sb0 + (c & 1) * STAGE_BIG;
    mma_tile<4>(acc, s, s + TBA, s + 2 * TBA, s + 3 * TBA, wm * 64, wn * 32);
    __syncthreads();
  }

  int g = lane >> 2, tq = (lane & 3) * 2;
  #pragma unroll
  for (int mi = 0; mi < 4; ++mi)
    #pragma unroll
    for (int ni = 0; ni < 4; ++ni) {
      int row = m0 + wm * 64 + mi * 16 + g;
      int col = n0 + wn * 32 + ni * 8 + tq;
      float2 bb = *reinterpret_cast<const float2*>(&b_proj[col]);
      *reinterpret_cast<float2*>(&out[(size_t)row * D + col]) =
          make_float2(acc[mi][ni][0] + bb.x, acc[mi][ni][1] + bb.y);
      *reinterpret_cast<float2*>(&out[(size_t)(row + 8) * D + col]) =
          make_float2(acc[mi][ni][2] + bb.x, acc[mi][ni][3] + bb.y);
    }
}

// ---------------------------------------------------------------------------
extern "C" void kernel_launch(void* const* d_in, const int* in_sizes, int n_in,
                              void* d_out, int out_size) {
  const float* query  = (const float*)d_in[0];
  const float* key    = (const float*)d_in[1];
  const float* value  = (const float*)d_in[2];
  const float* w_q    = (const float*)d_in[3];
  const float* w_k    = (const float*)d_in[4];
  const float* w_v    = (const float*)d_in[5];
  const float* w_proj = (const float*)d_in[6];
  const float* b_proj = (const float*)d_in[7];

  float* out   = (float*)d_out;
  float* attns = out + (size_t)B * SQ * D;

  static bool attr_done = false;
  if (!attr_done) {
    cudaFuncSetAttribute(proj_gemm,    cudaFuncAttributeMaxDynamicSharedMemorySize, SMEM_PIPE);
    cudaFuncSetAttribute(scores_gemm,  cudaFuncAttributeMaxDynamicSharedMemorySize, SMEM_SC);
    cudaFuncSetAttribute(av_gemm,      cudaFuncAttributeMaxDynamicSharedMemorySize, SMEM_AV);
    cudaFuncSetAttribute(outproj_gemm, cudaFuncAttributeMaxDynamicSharedMemorySize, SMEM_PIPE);
    attr_done = true;
  }

  conv_x <<<dim3(4096, 3), 256>>>(query, key, value);
  conv_w <<<dim3(1024, 3), 256>>>(w_q, w_k, w_v);
  conv_wp<<<dim3(1024, 1), 256>>>(w_proj);

  proj_gemm   <<<dim3(8, 8, 12), 256, SMEM_PIPE>>>();
  scores_gemm <<<dim3(8, 8, 64), 256, SMEM_SC>>>(attns);
  softmax_kernel<<<H * B * SQ, 256>>>(attns);
  av_gemm     <<<dim3(1, 4, 64), 256, SMEM_AV>>>();
  outproj_gemm<<<dim3(8, 32, 1), 256, SMEM_PIPE>>>(b_proj, out);
}